// round 13
// baseline (speedup 1.0000x reference)
#include <cuda_runtime.h>
#include <cuda_fp16.h>
#include <math.h>

#define NN   100000
#define EE   1600000
#define FIN  128
#define HID  64
#define CLS  16

// ---------------- scratch (static __device__ allocations) -------------------
// INVARIANT: g_deg is all-zero at kernel_launch entry (zero-initialized at
// load; re-zeroed at the tail of every call, off the critical path).
__device__ int    g_deg[NN];
__device__ int    g_rowstart[NN + 1];
__device__ int    g_cursor[NN];
__device__ int    g_edge[EE];                // src only, sorted by dst
__device__ int    g_blocksum[128];
__device__ float  g_dinv[NN];
__device__ __half g_h1h[(size_t)NN * HID];   // x@W1, then scaled by dinv (k_scale)
__device__ __half g_h2sh[(size_t)NN * CLS];  // (relu-out1@W2)*dinv fp16 messages

// ---------------- tail cleanup ----------------------------------------------
__global__ void k_tail_zero(int n) {
    int i = blockIdx.x * blockDim.x + threadIdx.x;
    if (i < n) g_deg[i] = 0;
}

// ---------------- degree (4 edges/thread, int4 load for MLP) ----------------
__global__ void k_deg(const int* __restrict__ dst, int E) {
    int i = (blockIdx.x * blockDim.x + threadIdx.x) * 4;
    if (i + 3 < E) {
        int4 d = *(const int4*)(dst + i);
        atomicAdd(&g_deg[d.x], 1);
        atomicAdd(&g_deg[d.y], 1);
        atomicAdd(&g_deg[d.z], 1);
        atomicAdd(&g_deg[d.w], 1);
    } else {
        for (int e = i; e < E; e++) atomicAdd(&g_deg[dst[e]], 1);
    }
}

// ---------------- CSR build (two-kernel scan, proven) ------------------------
__global__ __launch_bounds__(1024) void k_scanA(int N) {
    __shared__ int sh[1024];
    int i = blockIdx.x * 1024 + threadIdx.x;
    sh[threadIdx.x] = (i < N) ? g_deg[i] : 0;
    __syncthreads();
    #pragma unroll
    for (int off = 512; off; off >>= 1) {
        if (threadIdx.x < off) sh[threadIdx.x] += sh[threadIdx.x + off];
        __syncthreads();
    }
    if (threadIdx.x == 0) g_blocksum[blockIdx.x] = sh[0];
}

__global__ __launch_bounds__(1024) void k_scanC(int N, int E, int nb) {
    __shared__ int sh[1024];
    __shared__ int bs[128];
    const int tid = threadIdx.x;
    int i = blockIdx.x * 1024 + tid;
    int v = (i < N) ? g_deg[i] : 0;
    sh[tid] = v;
    if (tid < 128) bs[tid] = (tid < nb) ? g_blocksum[tid] : 0;
    __syncthreads();
    #pragma unroll
    for (int off = 1; off < 128; off <<= 1) {
        int x = 0;
        if (tid < 128 && tid >= off) x = bs[tid - off];
        __syncthreads();
        if (tid < 128) bs[tid] += x;
        __syncthreads();
    }
    #pragma unroll
    for (int off = 1; off < 1024; off <<= 1) {
        int x = (tid >= off) ? sh[tid - off] : 0;
        __syncthreads();
        sh[tid] += x;
        __syncthreads();
    }
    int blockpref = (blockIdx.x == 0) ? 0 : bs[blockIdx.x - 1];
    int excl = sh[tid] - v + blockpref;
    if (i < N) {
        g_rowstart[i] = excl;
        g_cursor[i]   = excl;
        g_dinv[i]     = rsqrtf((float)v + 1.0f);
    }
    if (i == 0) g_rowstart[N] = E;
}

// ---------------- reorder (cursor-based, 4 edges/thread) ---------------------
__global__ void k_reorder(const int* __restrict__ src, const int* __restrict__ dst, int E) {
    int i = (blockIdx.x * blockDim.x + threadIdx.x) * 4;
    if (i + 3 < E) {
        int4 d = *(const int4*)(dst + i);
        int4 s = *(const int4*)(src + i);
        int p0 = atomicAdd(&g_cursor[d.x], 1);
        int p1 = atomicAdd(&g_cursor[d.y], 1);
        int p2 = atomicAdd(&g_cursor[d.z], 1);
        int p3 = atomicAdd(&g_cursor[d.w], 1);
        g_edge[p0] = s.x;
        g_edge[p1] = s.y;
        g_edge[p2] = s.z;
        g_edge[p3] = s.w;
    } else {
        for (int e = i; e < E; e++) {
            int pos = atomicAdd(&g_cursor[dst[e]], 1);
            g_edge[pos] = src[e];
        }
    }
}

// ---------------- scale messages: h1h[i,:] *= dinv[i] (fp32 math) ------------
__global__ void k_scale(int N) {
    int u = blockIdx.x * blockDim.x + threadIdx.x;   // over N*8
    if (u >= N * 8) return;
    int node = u >> 3;
    float dv = g_dinv[node];
    uint4* p = (uint4*)(g_h1h) + u;
    uint4 q = *p;
    __half2* h = (__half2*)&q;
    #pragma unroll
    for (int k = 0; k < 4; k++) {
        float2 f = __half22float2(h[k]);
        h[k] = __floats2half2_rn(f.x * dv, f.y * dv);
    }
    *p = q;
}

// ---------------- GEMM1 via 3xTF32 tensor cores (h1 = x @ W1, fp16 out) -----
__device__ __forceinline__ unsigned f2tf32(float f) {
    unsigned r;
    asm("cvt.rna.tf32.f32 %0, %1;" : "=r"(r) : "f"(f));
    return r;
}

#define PITCH 132
#define GEMM1_SMEM (3 * 64 * PITCH * 4)

__global__ __launch_bounds__(128) void k_gemm1(const float* __restrict__ x,
                                               const float* __restrict__ W1, int N) {
    extern __shared__ float smem[];
    float*    sA  = smem;
    unsigned* sBh = (unsigned*)(smem + 64 * PITCH);
    unsigned* sBl = (unsigned*)(smem + 2 * 64 * PITCH);

    const int tid  = threadIdx.x;
    const int node0 = blockIdx.x * 64;

    for (int i = tid; i < 64 * 32; i += 128) {
        int r = i >> 5, c4 = i & 31;
        int node = node0 + r; if (node >= N) node = N - 1;
        float4 v = ((const float4*)(x + (size_t)node * FIN))[c4];
        float* p = sA + r * PITCH + c4 * 4;
        p[0] = v.x; p[1] = v.y; p[2] = v.z; p[3] = v.w;
    }
    for (int i = tid; i < FIN * HID; i += 128) {
        int k = i >> 6, n = i & 63;
        float w = W1[i];
        unsigned hi = f2tf32(w);
        float lo_f = w - __uint_as_float(hi);
        sBh[n * PITCH + k] = hi;
        sBl[n * PITCH + k] = f2tf32(lo_f);
    }
    __syncthreads();

    const int warp = tid >> 5;
    const int lane = tid & 31;
    const int g = lane >> 2;
    const int r = lane & 3;
    const int row0 = warp * 16 + g;
    const int row1 = row0 + 8;

    float acc[8][4];
    #pragma unroll
    for (int t = 0; t < 8; t++)
        #pragma unroll
        for (int j = 0; j < 4; j++) acc[t][j] = 0.f;

    #pragma unroll
    for (int kt = 0; kt < 16; kt++) {
        const int k0 = kt * 8;
        float a0f = sA[row0 * PITCH + k0 + r];
        float a1f = sA[row1 * PITCH + k0 + r];
        float a2f = sA[row0 * PITCH + k0 + 4 + r];
        float a3f = sA[row1 * PITCH + k0 + 4 + r];
        unsigned ah0 = f2tf32(a0f), ah1 = f2tf32(a1f), ah2 = f2tf32(a2f), ah3 = f2tf32(a3f);
        unsigned al0 = f2tf32(a0f - __uint_as_float(ah0));
        unsigned al1 = f2tf32(a1f - __uint_as_float(ah1));
        unsigned al2 = f2tf32(a2f - __uint_as_float(ah2));
        unsigned al3 = f2tf32(a3f - __uint_as_float(ah3));

        #pragma unroll
        for (int t = 0; t < 8; t++) {
            const unsigned* bhp = sBh + (t * 8 + g) * PITCH + k0;
            const unsigned* blp = sBl + (t * 8 + g) * PITCH + k0;
            unsigned bh0 = bhp[r], bh1 = bhp[4 + r];
            unsigned bl0 = blp[r], bl1 = blp[4 + r];
            asm("mma.sync.aligned.m16n8k8.row.col.f32.tf32.tf32.f32 "
                "{%0,%1,%2,%3},{%4,%5,%6,%7},{%8,%9},{%0,%1,%2,%3};"
                : "+f"(acc[t][0]), "+f"(acc[t][1]), "+f"(acc[t][2]), "+f"(acc[t][3])
                : "r"(ah0), "r"(ah1), "r"(ah2), "r"(ah3), "r"(bh0), "r"(bh1));
            asm("mma.sync.aligned.m16n8k8.row.col.f32.tf32.tf32.f32 "
                "{%0,%1,%2,%3},{%4,%5,%6,%7},{%8,%9},{%0,%1,%2,%3};"
                : "+f"(acc[t][0]), "+f"(acc[t][1]), "+f"(acc[t][2]), "+f"(acc[t][3])
                : "r"(al0), "r"(al1), "r"(al2), "r"(al3), "r"(bh0), "r"(bh1));
            asm("mma.sync.aligned.m16n8k8.row.col.f32.tf32.tf32.f32 "
                "{%0,%1,%2,%3},{%4,%5,%6,%7},{%8,%9},{%0,%1,%2,%3};"
                : "+f"(acc[t][0]), "+f"(acc[t][1]), "+f"(acc[t][2]), "+f"(acc[t][3])
                : "r"(ah0), "r"(ah1), "r"(ah2), "r"(ah3), "r"(bl0), "r"(bl1));
        }
    }

    int n0 = node0 + row0;
    int n1 = node0 + row1;
    #pragma unroll
    for (int t = 0; t < 8; t++) {
        int col = t * 8 + 2 * r;
        if (n0 < N)
            *(__half2*)(g_h1h + (size_t)n0 * HID + col) = __floats2half2_rn(acc[t][0], acc[t][1]);
        if (n1 < N)
            *(__half2*)(g_h1h + (size_t)n1 * HID + col) = __floats2half2_rn(acc[t][2], acc[t][3]);
    }
}

// ---------------- agg1 + gemm2 fused (R11-proven block-level form) -----------
__global__ __launch_bounds__(256) void k_agg1f(const float* __restrict__ b1,
                                               const float* __restrict__ W2, int N) {
    __shared__ float xs[8][HID];
    __shared__ float W2s[HID * CLS];
    __shared__ float dd[8];

    const int tid  = threadIdx.x;
    const int warp = tid >> 5;
    const int lane = tid & 31;
    const int node = blockIdx.x * 8 + warp;

    for (int i = tid; i < HID * CLS; i += 256) W2s[i] = W2[i];

    if (node < N) {
        int rs = __ldg(&g_rowstart[node]), re = __ldg(&g_rowstart[node + 1]);
        float dw = g_dinv[node];

        // self term: h1h is pre-scaled => dinv_i * h1[i]
        float2 acc = __half22float2(((const __half2*)(g_h1h + (size_t)node * HID))[lane]);

        for (int base = rs; base < re; base += 32) {
            int n = re - base;
            int idx = (lane < n) ? g_edge[base + lane] : 0;
            int cnt = n < 32 ? n : 32;
            int j = 0;
            for (; j + 8 <= cnt; j += 8) {
                int s0 = __shfl_sync(0xffffffffu, idx, j);
                int s1 = __shfl_sync(0xffffffffu, idx, j + 1);
                int s2 = __shfl_sync(0xffffffffu, idx, j + 2);
                int s3 = __shfl_sync(0xffffffffu, idx, j + 3);
                int s4 = __shfl_sync(0xffffffffu, idx, j + 4);
                int s5 = __shfl_sync(0xffffffffu, idx, j + 5);
                int s6 = __shfl_sync(0xffffffffu, idx, j + 6);
                int s7 = __shfl_sync(0xffffffffu, idx, j + 7);
                float2 v0 = __half22float2(((const __half2*)(g_h1h + (size_t)s0 * HID))[lane]);
                float2 v1 = __half22float2(((const __half2*)(g_h1h + (size_t)s1 * HID))[lane]);
                float2 v2 = __half22float2(((const __half2*)(g_h1h + (size_t)s2 * HID))[lane]);
                float2 v3 = __half22float2(((const __half2*)(g_h1h + (size_t)s3 * HID))[lane]);
                float2 v4 = __half22float2(((const __half2*)(g_h1h + (size_t)s4 * HID))[lane]);
                float2 v5 = __half22float2(((const __half2*)(g_h1h + (size_t)s5 * HID))[lane]);
                float2 v6 = __half22float2(((const __half2*)(g_h1h + (size_t)s6 * HID))[lane]);
                float2 v7 = __half22float2(((const __half2*)(g_h1h + (size_t)s7 * HID))[lane]);
                acc.x += v0.x + v1.x + v2.x + v3.x + v4.x + v5.x + v6.x + v7.x;
                acc.y += v0.y + v1.y + v2.y + v3.y + v4.y + v5.y + v6.y + v7.y;
            }
            for (; j < cnt; j++) {
                int s = __shfl_sync(0xffffffffu, idx, j);
                float2 v = __half22float2(((const __half2*)(g_h1h + (size_t)s * HID))[lane]);
                acc.x += v.x; acc.y += v.y;
            }
        }

        float2 bb = ((const float2*)b1)[lane];
        xs[warp][2 * lane]     = fmaxf(fmaf(dw, acc.x, bb.x), 0.f);
        xs[warp][2 * lane + 1] = fmaxf(fmaf(dw, acc.y, bb.y), 0.f);
        if (lane == 0) dd[warp] = dw;
    }
    __syncthreads();

    if (tid < 128) {
        int nn  = tid >> 4;
        int cls = tid & 15;
        int gnode = blockIdx.x * 8 + nn;
        if (gnode < N) {
            float a = 0.f;
            #pragma unroll 16
            for (int k = 0; k < HID; k++)
                a += xs[nn][k] * W2s[k * CLS + cls];
            g_h2sh[(size_t)gnode * CLS + cls] = __float2half_rn(a * dd[nn]);
        }
    }
}

// ---------------- agg2 + combine + log_softmax ------------------------------
__global__ __launch_bounds__(256) void k_agg2(const float* __restrict__ b2,
                                              float* __restrict__ out, int N) {
    int g = (blockIdx.x * 256 + threadIdx.x) >> 4;
    int lane = threadIdx.x & 15;
    int seg = (threadIdx.x >> 4) & 1;
    unsigned mask = 0xFFFFu << (seg * 16);
    if (g >= N) return;

    int rs = __ldg(&g_rowstart[g]), re = __ldg(&g_rowstart[g + 1]);
    float acc = __half2float(g_h2sh[(size_t)g * CLS + lane]);   // self term

    for (int base = rs; base < re; base += 16) {
        int n = re - base;
        int idx = (lane < n) ? g_edge[base + lane] : 0;
        int cnt = n < 16 ? n : 16;
        int j = 0;
        for (; j + 8 <= cnt; j += 8) {
            int s0 = __shfl_sync(mask, idx, j, 16);
            int s1 = __shfl_sync(mask, idx, j + 1, 16);
            int s2 = __shfl_sync(mask, idx, j + 2, 16);
            int s3 = __shfl_sync(mask, idx, j + 3, 16);
            int s4 = __shfl_sync(mask, idx, j + 4, 16);
            int s5 = __shfl_sync(mask, idx, j + 5, 16);
            int s6 = __shfl_sync(mask, idx, j + 6, 16);
            int s7 = __shfl_sync(mask, idx, j + 7, 16);
            float v0 = __half2float(g_h2sh[(size_t)s0 * CLS + lane]);
            float v1 = __half2float(g_h2sh[(size_t)s1 * CLS + lane]);
            float v2 = __half2float(g_h2sh[(size_t)s2 * CLS + lane]);
            float v3 = __half2float(g_h2sh[(size_t)s3 * CLS + lane]);
            float v4 = __half2float(g_h2sh[(size_t)s4 * CLS + lane]);
            float v5 = __half2float(g_h2sh[(size_t)s5 * CLS + lane]);
            float v6 = __half2float(g_h2sh[(size_t)s6 * CLS + lane]);
            float v7 = __half2float(g_h2sh[(size_t)s7 * CLS + lane]);
            acc += v0 + v1 + v2 + v3 + v4 + v5 + v6 + v7;
        }
        for (; j < cnt; j++) {
            int s = __shfl_sync(mask, idx, j, 16);
            acc += __half2float(g_h2sh[(size_t)s * CLS + lane]);
        }
    }

    float d = g_dinv[g];
    float z = fmaxf(fmaf(d, acc, b2[lane]), 0.f);

    float m = z;
    #pragma unroll
    for (int off = 8; off; off >>= 1) m = fmaxf(m, __shfl_xor_sync(mask, m, off, 16));
    float e = expf(z - m);
    float ssum = e;
    #pragma unroll
    for (int off = 8; off; off >>= 1) ssum += __shfl_xor_sync(mask, ssum, off, 16);

    out[(size_t)g * CLS + lane] = z - (m + logf(ssum));
}

// ---------------- launcher ---------------------------------------------------
extern "C" void kernel_launch(void* const* d_in, const int* in_sizes, int n_in,
                              void* d_out, int out_size) {
    const float* x  = (const float*)d_in[0];
    const int*   ei = (const int*)d_in[1];
    const float* W1 = (const float*)d_in[2];
    const float* b1 = (const float*)d_in[3];
    const float* W2 = (const float*)d_in[4];
    const float* b2 = (const float*)d_in[5];
    float* out = (float*)d_out;

    const int N = in_sizes[0] / FIN;       // 100000
    const int E = in_sizes[1] / 2;         // 1600000
    const int* src = ei;
    const int* dst = ei + E;
    const int nb = (N + 1023) / 1024;
    const int e4blocks = (E / 4 + 255) / 256;

    static cudaStream_t s2 = nullptr;
    static cudaEvent_t evFork = nullptr, evCsr = nullptr, evScale = nullptr, evTail = nullptr;
    static int init_done = 0;
    if (!init_done) {
        cudaFuncSetAttribute(k_gemm1, cudaFuncAttributeMaxDynamicSharedMemorySize, GEMM1_SMEM);
        cudaStreamCreateWithFlags(&s2, cudaStreamNonBlocking);
        cudaEventCreateWithFlags(&evFork, cudaEventDisableTiming);
        cudaEventCreateWithFlags(&evCsr, cudaEventDisableTiming);
        cudaEventCreateWithFlags(&evScale, cudaEventDisableTiming);
        cudaEventCreateWithFlags(&evTail, cudaEventDisableTiming);
        init_done = 1;
    }

    // Fork: gemm1 (x,W1 only) on s2, concurrent with the CSR build chain.
    cudaEventRecord(evFork, 0);
    cudaStreamWaitEvent(s2, evFork, 0);
    k_gemm1<<<(N + 63) / 64, 128, GEMM1_SMEM, s2>>>(x, W1, N);

    // CSR build chain on main stream (g_deg is zero at entry per invariant).
    k_deg<<<e4blocks, 256>>>(dst, E);
    k_scanA<<<nb, 1024>>>(N);
    k_scanC<<<nb, 1024>>>(N, E, nb);
    cudaEventRecord(evCsr, 0);           // dinv + rowstart + cursor ready

    // s2: after gemm1 (stream order) AND scanC (event): scale messages,
    // then restore g_deg == 0 (already consumed by scanC).
    cudaStreamWaitEvent(s2, evCsr, 0);
    k_scale<<<(N * 8 + 255) / 256, 256, 0, s2>>>(N);
    cudaEventRecord(evScale, s2);
    k_tail_zero<<<(N + 255) / 256, 256, 0, s2>>>(N);
    cudaEventRecord(evTail, s2);

    // Main stream: reorder (needs scanC, stream-ordered) concurrent with k_scale.
    k_reorder<<<e4blocks, 256>>>(src, dst, E);

    // Join: agg1f needs scaled h1h and the sorted edges.
    cudaStreamWaitEvent(0, evScale, 0);

    k_agg1f<<<(N + 7) / 8, 256>>>(b1, W2, N);

    {
        long long units = (long long)N * 16;
        k_agg2<<<(unsigned)((units + 255) / 256), 256>>>(b2, out, N);
    }

    // Re-join s2 so the capture graph is fully joined to the origin stream.
    cudaStreamWaitEvent(0, evTail, 0);
}

// round 14
// speedup vs baseline: 1.5114x; 1.5114x over previous
#include <cuda_runtime.h>
#include <cuda_fp16.h>
#include <math.h>

#define NN   100000
#define EE   1600000
#define FIN  128
#define HID  64
#define CLS  16

// ---------------- scratch (static __device__ allocations) -------------------
// INVARIANT: g_deg is all-zero at kernel_launch entry (zero-initialized at
// load; re-zeroed at the tail of every call, off the critical path).
__device__ int    g_deg[NN];
__device__ int    g_rowstart[NN + 1];
__device__ int    g_cursor[NN];
__device__ int    g_edge[EE];                // src only, sorted by dst
__device__ int    g_blocksum[128];
__device__ float  g_dinv[NN];
__device__ __half g_h1h[(size_t)NN * HID];   // x@W1, then scaled by dinv (k_scale)
__device__ __half g_h2sh[(size_t)NN * CLS];  // (relu-out1@W2)*dinv fp16 messages

// ---------------- tail cleanup ----------------------------------------------
__global__ void k_tail_zero(int n) {
    int i = blockIdx.x * blockDim.x + threadIdx.x;
    if (i < n) g_deg[i] = 0;
}

// ---------------- degree ----------------------------------------------------
__global__ void k_deg(const int* __restrict__ dst, int E) {
    int e = blockIdx.x * blockDim.x + threadIdx.x;
    if (e < E) atomicAdd(&g_deg[dst[e]], 1);
}

// ---------------- CSR build (two-kernel scan, proven) ------------------------
__global__ __launch_bounds__(1024) void k_scanA(int N) {
    __shared__ int sh[1024];
    int i = blockIdx.x * 1024 + threadIdx.x;
    sh[threadIdx.x] = (i < N) ? g_deg[i] : 0;
    __syncthreads();
    #pragma unroll
    for (int off = 512; off; off >>= 1) {
        if (threadIdx.x < off) sh[threadIdx.x] += sh[threadIdx.x + off];
        __syncthreads();
    }
    if (threadIdx.x == 0) g_blocksum[blockIdx.x] = sh[0];
}

__global__ __launch_bounds__(1024) void k_scanC(int N, int E, int nb) {
    __shared__ int sh[1024];
    __shared__ int bs[128];
    const int tid = threadIdx.x;
    int i = blockIdx.x * 1024 + tid;
    int v = (i < N) ? g_deg[i] : 0;
    sh[tid] = v;
    if (tid < 128) bs[tid] = (tid < nb) ? g_blocksum[tid] : 0;
    __syncthreads();
    #pragma unroll
    for (int off = 1; off < 128; off <<= 1) {
        int x = 0;
        if (tid < 128 && tid >= off) x = bs[tid - off];
        __syncthreads();
        if (tid < 128) bs[tid] += x;
        __syncthreads();
    }
    #pragma unroll
    for (int off = 1; off < 1024; off <<= 1) {
        int x = (tid >= off) ? sh[tid - off] : 0;
        __syncthreads();
        sh[tid] += x;
        __syncthreads();
    }
    int blockpref = (blockIdx.x == 0) ? 0 : bs[blockIdx.x - 1];
    int excl = sh[tid] - v + blockpref;
    if (i < N) {
        g_rowstart[i] = excl;
        g_cursor[i]   = excl;
        g_dinv[i]     = rsqrtf((float)v + 1.0f);
    }
    if (i == 0) g_rowstart[N] = E;
}

// ---------------- reorder (cursor-based, src-only payload) -------------------
__global__ void k_reorder(const int* __restrict__ src, const int* __restrict__ dst, int E) {
    int e = blockIdx.x * blockDim.x + threadIdx.x;
    if (e < E) {
        int d = dst[e];
        int pos = atomicAdd(&g_cursor[d], 1);
        g_edge[pos] = src[e];
    }
}

// ---------------- scale messages: h1h[i,:] *= dinv[i] (fp32 math) ------------
__global__ void k_scale(int N) {
    int u = blockIdx.x * blockDim.x + threadIdx.x;   // over N*8
    if (u >= N * 8) return;
    int node = u >> 3;
    float dv = g_dinv[node];
    uint4* p = (uint4*)(g_h1h) + u;
    uint4 q = *p;
    __half2* h = (__half2*)&q;
    #pragma unroll
    for (int k = 0; k < 4; k++) {
        float2 f = __half22float2(h[k]);
        h[k] = __floats2half2_rn(f.x * dv, f.y * dv);
    }
    *p = q;
}

// ---------------- GEMM1 via 3xTF32 tensor cores (h1 = x @ W1, fp16 out) -----
__device__ __forceinline__ unsigned f2tf32(float f) {
    unsigned r;
    asm("cvt.rna.tf32.f32 %0, %1;" : "=r"(r) : "f"(f));
    return r;
}

#define PITCH 132
#define GEMM1_SMEM (3 * 64 * PITCH * 4)

__global__ __launch_bounds__(128) void k_gemm1(const float* __restrict__ x,
                                               const float* __restrict__ W1, int N) {
    extern __shared__ float smem[];
    float*    sA  = smem;
    unsigned* sBh = (unsigned*)(smem + 64 * PITCH);
    unsigned* sBl = (unsigned*)(smem + 2 * 64 * PITCH);

    const int tid  = threadIdx.x;
    const int node0 = blockIdx.x * 64;

    for (int i = tid; i < 64 * 32; i += 128) {
        int r = i >> 5, c4 = i & 31;
        int node = node0 + r; if (node >= N) node = N - 1;
        float4 v = ((const float4*)(x + (size_t)node * FIN))[c4];
        float* p = sA + r * PITCH + c4 * 4;
        p[0] = v.x; p[1] = v.y; p[2] = v.z; p[3] = v.w;
    }
    for (int i = tid; i < FIN * HID; i += 128) {
        int k = i >> 6, n = i & 63;
        float w = W1[i];
        unsigned hi = f2tf32(w);
        float lo_f = w - __uint_as_float(hi);
        sBh[n * PITCH + k] = hi;
        sBl[n * PITCH + k] = f2tf32(lo_f);
    }
    __syncthreads();

    const int warp = tid >> 5;
    const int lane = tid & 31;
    const int g = lane >> 2;
    const int r = lane & 3;
    const int row0 = warp * 16 + g;
    const int row1 = row0 + 8;

    float acc[8][4];
    #pragma unroll
    for (int t = 0; t < 8; t++)
        #pragma unroll
        for (int j = 0; j < 4; j++) acc[t][j] = 0.f;

    #pragma unroll
    for (int kt = 0; kt < 16; kt++) {
        const int k0 = kt * 8;
        float a0f = sA[row0 * PITCH + k0 + r];
        float a1f = sA[row1 * PITCH + k0 + r];
        float a2f = sA[row0 * PITCH + k0 + 4 + r];
        float a3f = sA[row1 * PITCH + k0 + 4 + r];
        unsigned ah0 = f2tf32(a0f), ah1 = f2tf32(a1f), ah2 = f2tf32(a2f), ah3 = f2tf32(a3f);
        unsigned al0 = f2tf32(a0f - __uint_as_float(ah0));
        unsigned al1 = f2tf32(a1f - __uint_as_float(ah1));
        unsigned al2 = f2tf32(a2f - __uint_as_float(ah2));
        unsigned al3 = f2tf32(a3f - __uint_as_float(ah3));

        #pragma unroll
        for (int t = 0; t < 8; t++) {
            const unsigned* bhp = sBh + (t * 8 + g) * PITCH + k0;
            const unsigned* blp = sBl + (t * 8 + g) * PITCH + k0;
            unsigned bh0 = bhp[r], bh1 = bhp[4 + r];
            unsigned bl0 = blp[r], bl1 = blp[4 + r];
            asm("mma.sync.aligned.m16n8k8.row.col.f32.tf32.tf32.f32 "
                "{%0,%1,%2,%3},{%4,%5,%6,%7},{%8,%9},{%0,%1,%2,%3};"
                : "+f"(acc[t][0]), "+f"(acc[t][1]), "+f"(acc[t][2]), "+f"(acc[t][3])
                : "r"(ah0), "r"(ah1), "r"(ah2), "r"(ah3), "r"(bh0), "r"(bh1));
            asm("mma.sync.aligned.m16n8k8.row.col.f32.tf32.tf32.f32 "
                "{%0,%1,%2,%3},{%4,%5,%6,%7},{%8,%9},{%0,%1,%2,%3};"
                : "+f"(acc[t][0]), "+f"(acc[t][1]), "+f"(acc[t][2]), "+f"(acc[t][3])
                : "r"(al0), "r"(al1), "r"(al2), "r"(al3), "r"(bh0), "r"(bh1));
            asm("mma.sync.aligned.m16n8k8.row.col.f32.tf32.tf32.f32 "
                "{%0,%1,%2,%3},{%4,%5,%6,%7},{%8,%9},{%0,%1,%2,%3};"
                : "+f"(acc[t][0]), "+f"(acc[t][1]), "+f"(acc[t][2]), "+f"(acc[t][3])
                : "r"(ah0), "r"(ah1), "r"(ah2), "r"(ah3), "r"(bl0), "r"(bl1));
        }
    }

    int n0 = node0 + row0;
    int n1 = node0 + row1;
    #pragma unroll
    for (int t = 0; t < 8; t++) {
        int col = t * 8 + 2 * r;
        if (n0 < N)
            *(__half2*)(g_h1h + (size_t)n0 * HID + col) = __floats2half2_rn(acc[t][0], acc[t][1]);
        if (n1 < N)
            *(__half2*)(g_h1h + (size_t)n1 * HID + col) = __floats2half2_rn(acc[t][2], acc[t][3]);
    }
}

// ---------------- agg1 + gemm2 fused (messages pre-scaled) -------------------
__global__ __launch_bounds__(256) void k_agg1f(const float* __restrict__ b1,
                                               const float* __restrict__ W2, int N) {
    __shared__ float xs[8][HID];
    __shared__ float W2s[HID * CLS];
    __shared__ float dd[8];

    const int tid  = threadIdx.x;
    const int warp = tid >> 5;
    const int lane = tid & 31;
    const int node = blockIdx.x * 8 + warp;

    for (int i = tid; i < HID * CLS; i += 256) W2s[i] = W2[i];

    if (node < N) {
        int rs = __ldg(&g_rowstart[node]), re = __ldg(&g_rowstart[node + 1]);
        float dw = g_dinv[node];

        // self term: h1h is pre-scaled, so this is dinv_i * h1[i] already
        float2 acc = __half22float2(((const __half2*)(g_h1h + (size_t)node * HID))[lane]);

        for (int base = rs; base < re; base += 32) {
            int n = re - base;
            int idx = (lane < n) ? g_edge[base + lane] : 0;
            int cnt = n < 32 ? n : 32;
            int j = 0;
            for (; j + 8 <= cnt; j += 8) {
                int s0 = __shfl_sync(0xffffffffu, idx, j);
                int s1 = __shfl_sync(0xffffffffu, idx, j + 1);
                int s2 = __shfl_sync(0xffffffffu, idx, j + 2);
                int s3 = __shfl_sync(0xffffffffu, idx, j + 3);
                int s4 = __shfl_sync(0xffffffffu, idx, j + 4);
                int s5 = __shfl_sync(0xffffffffu, idx, j + 5);
                int s6 = __shfl_sync(0xffffffffu, idx, j + 6);
                int s7 = __shfl_sync(0xffffffffu, idx, j + 7);
                float2 v0 = __half22float2(((const __half2*)(g_h1h + (size_t)s0 * HID))[lane]);
                float2 v1 = __half22float2(((const __half2*)(g_h1h + (size_t)s1 * HID))[lane]);
                float2 v2 = __half22float2(((const __half2*)(g_h1h + (size_t)s2 * HID))[lane]);
                float2 v3 = __half22float2(((const __half2*)(g_h1h + (size_t)s3 * HID))[lane]);
                float2 v4 = __half22float2(((const __half2*)(g_h1h + (size_t)s4 * HID))[lane]);
                float2 v5 = __half22float2(((const __half2*)(g_h1h + (size_t)s5 * HID))[lane]);
                float2 v6 = __half22float2(((const __half2*)(g_h1h + (size_t)s6 * HID))[lane]);
                float2 v7 = __half22float2(((const __half2*)(g_h1h + (size_t)s7 * HID))[lane]);
                acc.x += v0.x + v1.x + v2.x + v3.x + v4.x + v5.x + v6.x + v7.x;
                acc.y += v0.y + v1.y + v2.y + v3.y + v4.y + v5.y + v6.y + v7.y;
            }
            for (; j < cnt; j++) {
                int s = __shfl_sync(0xffffffffu, idx, j);
                float2 v = __half22float2(((const __half2*)(g_h1h + (size_t)s * HID))[lane]);
                acc.x += v.x; acc.y += v.y;
            }
        }

        float2 bb = ((const float2*)b1)[lane];
        xs[warp][2 * lane]     = fmaxf(fmaf(dw, acc.x, bb.x), 0.f);
        xs[warp][2 * lane + 1] = fmaxf(fmaf(dw, acc.y, bb.y), 0.f);
        if (lane == 0) dd[warp] = dw;
    }
    __syncthreads();

    if (tid < 128) {
        int nn  = tid >> 4;
        int cls = tid & 15;
        int gnode = blockIdx.x * 8 + nn;
        if (gnode < N) {
            float a = 0.f;
            #pragma unroll 16
            for (int k = 0; k < HID; k++)
                a += xs[nn][k] * W2s[k * CLS + cls];
            g_h2sh[(size_t)gnode * CLS + cls] = __float2half_rn(a * dd[nn]);
        }
    }
}

// ---------------- agg2 + combine + log_softmax ------------------------------
__global__ __launch_bounds__(256) void k_agg2(const float* __restrict__ b2,
                                              float* __restrict__ out, int N) {
    int g = (blockIdx.x * 256 + threadIdx.x) >> 4;
    int lane = threadIdx.x & 15;
    int seg = (threadIdx.x >> 4) & 1;
    unsigned mask = 0xFFFFu << (seg * 16);
    if (g >= N) return;

    int rs = __ldg(&g_rowstart[g]), re = __ldg(&g_rowstart[g + 1]);
    float acc = __half2float(g_h2sh[(size_t)g * CLS + lane]);   // self term

    for (int base = rs; base < re; base += 16) {
        int n = re - base;
        int idx = (lane < n) ? g_edge[base + lane] : 0;
        int cnt = n < 16 ? n : 16;
        int j = 0;
        for (; j + 8 <= cnt; j += 8) {
            int s0 = __shfl_sync(mask, idx, j, 16);
            int s1 = __shfl_sync(mask, idx, j + 1, 16);
            int s2 = __shfl_sync(mask, idx, j + 2, 16);
            int s3 = __shfl_sync(mask, idx, j + 3, 16);
            int s4 = __shfl_sync(mask, idx, j + 4, 16);
            int s5 = __shfl_sync(mask, idx, j + 5, 16);
            int s6 = __shfl_sync(mask, idx, j + 6, 16);
            int s7 = __shfl_sync(mask, idx, j + 7, 16);
            float v0 = __half2float(g_h2sh[(size_t)s0 * CLS + lane]);
            float v1 = __half2float(g_h2sh[(size_t)s1 * CLS + lane]);
            float v2 = __half2float(g_h2sh[(size_t)s2 * CLS + lane]);
            float v3 = __half2float(g_h2sh[(size_t)s3 * CLS + lane]);
            float v4 = __half2float(g_h2sh[(size_t)s4 * CLS + lane]);
            float v5 = __half2float(g_h2sh[(size_t)s5 * CLS + lane]);
            float v6 = __half2float(g_h2sh[(size_t)s6 * CLS + lane]);
            float v7 = __half2float(g_h2sh[(size_t)s7 * CLS + lane]);
            acc += v0 + v1 + v2 + v3 + v4 + v5 + v6 + v7;
        }
        for (; j < cnt; j++) {
            int s = __shfl_sync(mask, idx, j, 16);
            acc += __half2float(g_h2sh[(size_t)s * CLS + lane]);
        }
    }

    float d = g_dinv[g];
    float z = fmaxf(fmaf(d, acc, b2[lane]), 0.f);

    float m = z;
    #pragma unroll
    for (int off = 8; off; off >>= 1) m = fmaxf(m, __shfl_xor_sync(mask, m, off, 16));
    float e = expf(z - m);
    float ssum = e;
    #pragma unroll
    for (int off = 8; off; off >>= 1) ssum += __shfl_xor_sync(mask, ssum, off, 16);

    out[(size_t)g * CLS + lane] = z - (m + logf(ssum));
}

// ---------------- launcher ---------------------------------------------------
extern "C" void kernel_launch(void* const* d_in, const int* in_sizes, int n_in,
                              void* d_out, int out_size) {
    const float* x  = (const float*)d_in[0];
    const int*   ei = (const int*)d_in[1];
    const float* W1 = (const float*)d_in[2];
    const float* b1 = (const float*)d_in[3];
    const float* W2 = (const float*)d_in[4];
    const float* b2 = (const float*)d_in[5];
    float* out = (float*)d_out;

    const int N = in_sizes[0] / FIN;       // 100000
    const int E = in_sizes[1] / 2;         // 1600000
    const int* src = ei;
    const int* dst = ei + E;
    const int nb = (N + 1023) / 1024;

    static cudaStream_t s2 = nullptr;
    static cudaEvent_t evFork = nullptr, evCsr = nullptr, evScale = nullptr, evTail = nullptr;
    static int init_done = 0;
    if (!init_done) {
        cudaFuncSetAttribute(k_gemm1, cudaFuncAttributeMaxDynamicSharedMemorySize, GEMM1_SMEM);
        cudaStreamCreateWithFlags(&s2, cudaStreamNonBlocking);
        cudaEventCreateWithFlags(&evFork, cudaEventDisableTiming);
        cudaEventCreateWithFlags(&evCsr, cudaEventDisableTiming);
        cudaEventCreateWithFlags(&evScale, cudaEventDisableTiming);
        cudaEventCreateWithFlags(&evTail, cudaEventDisableTiming);
        init_done = 1;
    }

    // Fork: gemm1 (x,W1 only) on s2, concurrent with the CSR build chain.
    cudaEventRecord(evFork, 0);
    cudaStreamWaitEvent(s2, evFork, 0);
    k_gemm1<<<(N + 63) / 64, 128, GEMM1_SMEM, s2>>>(x, W1, N);

    // CSR build chain on main stream (g_deg is zero at entry per invariant).
    k_deg<<<(E + 255) / 256, 256>>>(dst, E);
    k_scanA<<<nb, 1024>>>(N);
    k_scanC<<<nb, 1024>>>(N, E, nb);
    cudaEventRecord(evCsr, 0);           // dinv + rowstart + cursor ready

    // s2: after gemm1 (stream order) AND scanC (event): scale messages,
    // then restore g_deg == 0 (already consumed by scanC).
    cudaStreamWaitEvent(s2, evCsr, 0);
    k_scale<<<(N * 8 + 255) / 256, 256, 0, s2>>>(N);
    cudaEventRecord(evScale, s2);
    k_tail_zero<<<(N + 255) / 256, 256, 0, s2>>>(N);
    cudaEventRecord(evTail, s2);

    // Main stream: reorder (needs scanC, stream-ordered) concurrent with k_scale.
    k_reorder<<<(E + 255) / 256, 256>>>(src, dst, E);

    // Join: agg1f needs scaled h1h and the sorted edges.
    cudaStreamWaitEvent(0, evScale, 0);

    k_agg1f<<<(N + 7) / 8, 256>>>(b1, W2, N);

    {
        long long units = (long long)N * 16;
        k_agg2<<<(unsigned)((units + 255) / 256), 256>>>(b2, out, N);
    }

    // Re-join s2 so the capture graph is fully joined to the origin stream.
    cudaStreamWaitEvent(0, evTail, 0);
}

// round 15
// speedup vs baseline: 1.6021x; 1.0600x over previous
#include <cuda_runtime.h>
#include <cuda_fp16.h>
#include <math.h>

#define NN   100000
#define EE   1600000
#define FIN  128
#define HID  64
#define CLS  16

// ---------------- scratch (static __device__ allocations) -------------------
// INVARIANT: g_deg is all-zero at kernel_launch entry (zero-initialized at
// load; re-zeroed at the tail of every call, off the critical path).
__device__ int    g_deg[NN];
__device__ int    g_rowstart[NN + 1];
__device__ int    g_cursor[NN];
__device__ int    g_edge[EE];                // src only, sorted by dst
__device__ int    g_blocksum[128];
__device__ float  g_dinv[NN];
__device__ __half g_h1h[(size_t)NN * HID];   // x@W1, then scaled by dinv (k_scale)
__device__ __half g_h2sh[(size_t)NN * CLS];  // (relu-out1@W2)*dinv fp16 messages

// ---------------- tail cleanup ----------------------------------------------
__global__ void k_tail_zero(int n) {
    int i = blockIdx.x * blockDim.x + threadIdx.x;
    if (i < n) g_deg[i] = 0;
}

// ---------------- degree ----------------------------------------------------
__global__ void k_deg(const int* __restrict__ dst, int E) {
    int e = blockIdx.x * blockDim.x + threadIdx.x;
    if (e < E) atomicAdd(&g_deg[dst[e]], 1);
}

// ---------------- CSR build (two-kernel scan, proven) ------------------------
__global__ __launch_bounds__(1024) void k_scanA(int N) {
    __shared__ int sh[1024];
    int i = blockIdx.x * 1024 + threadIdx.x;
    sh[threadIdx.x] = (i < N) ? g_deg[i] : 0;
    __syncthreads();
    #pragma unroll
    for (int off = 512; off; off >>= 1) {
        if (threadIdx.x < off) sh[threadIdx.x] += sh[threadIdx.x + off];
        __syncthreads();
    }
    if (threadIdx.x == 0) g_blocksum[blockIdx.x] = sh[0];
}

__global__ __launch_bounds__(1024) void k_scanC(int N, int E, int nb) {
    __shared__ int sh[1024];
    __shared__ int bs[128];
    const int tid = threadIdx.x;
    int i = blockIdx.x * 1024 + tid;
    int v = (i < N) ? g_deg[i] : 0;
    sh[tid] = v;
    if (tid < 128) bs[tid] = (tid < nb) ? g_blocksum[tid] : 0;
    __syncthreads();
    #pragma unroll
    for (int off = 1; off < 128; off <<= 1) {
        int x = 0;
        if (tid < 128 && tid >= off) x = bs[tid - off];
        __syncthreads();
        if (tid < 128) bs[tid] += x;
        __syncthreads();
    }
    #pragma unroll
    for (int off = 1; off < 1024; off <<= 1) {
        int x = (tid >= off) ? sh[tid - off] : 0;
        __syncthreads();
        sh[tid] += x;
        __syncthreads();
    }
    int blockpref = (blockIdx.x == 0) ? 0 : bs[blockIdx.x - 1];
    int excl = sh[tid] - v + blockpref;
    if (i < N) {
        g_rowstart[i] = excl;
        g_cursor[i]   = excl;
        g_dinv[i]     = rsqrtf((float)v + 1.0f);
    }
    if (i == 0) g_rowstart[N] = E;
}

// ---------------- reorder (cursor-based, src-only payload) -------------------
__global__ void k_reorder(const int* __restrict__ src, const int* __restrict__ dst, int E) {
    int e = blockIdx.x * blockDim.x + threadIdx.x;
    if (e < E) {
        int d = dst[e];
        int pos = atomicAdd(&g_cursor[d], 1);
        g_edge[pos] = src[e];
    }
}

// ---------------- scale messages: h1h[i,:] *= dinv[i] (fp32 math) ------------
__global__ void k_scale(int N) {
    int u = blockIdx.x * blockDim.x + threadIdx.x;   // over N*8
    if (u >= N * 8) return;
    int node = u >> 3;
    float dv = g_dinv[node];
    uint4* p = (uint4*)(g_h1h) + u;
    uint4 q = *p;
    __half2* h = (__half2*)&q;
    #pragma unroll
    for (int k = 0; k < 4; k++) {
        float2 f = __half22float2(h[k]);
        h[k] = __floats2half2_rn(f.x * dv, f.y * dv);
    }
    *p = q;
}

// ---------------- GEMM1 via 3xTF32 tensor cores (h1 = x @ W1, fp16 out) -----
__device__ __forceinline__ unsigned f2tf32(float f) {
    unsigned r;
    asm("cvt.rna.tf32.f32 %0, %1;" : "=r"(r) : "f"(f));
    return r;
}

#define PITCH 132
#define GEMM1_SMEM (3 * 64 * PITCH * 4)

__global__ __launch_bounds__(128) void k_gemm1(const float* __restrict__ x,
                                               const float* __restrict__ W1, int N) {
    extern __shared__ float smem[];
    float*    sA  = smem;
    unsigned* sBh = (unsigned*)(smem + 64 * PITCH);
    unsigned* sBl = (unsigned*)(smem + 2 * 64 * PITCH);

    const int tid  = threadIdx.x;
    const int node0 = blockIdx.x * 64;

    for (int i = tid; i < 64 * 32; i += 128) {
        int r = i >> 5, c4 = i & 31;
        int node = node0 + r; if (node >= N) node = N - 1;
        float4 v = ((const float4*)(x + (size_t)node * FIN))[c4];
        float* p = sA + r * PITCH + c4 * 4;
        p[0] = v.x; p[1] = v.y; p[2] = v.z; p[3] = v.w;
    }
    for (int i = tid; i < FIN * HID; i += 128) {
        int k = i >> 6, n = i & 63;
        float w = W1[i];
        unsigned hi = f2tf32(w);
        float lo_f = w - __uint_as_float(hi);
        sBh[n * PITCH + k] = hi;
        sBl[n * PITCH + k] = f2tf32(lo_f);
    }
    __syncthreads();

    const int warp = tid >> 5;
    const int lane = tid & 31;
    const int g = lane >> 2;
    const int r = lane & 3;
    const int row0 = warp * 16 + g;
    const int row1 = row0 + 8;

    float acc[8][4];
    #pragma unroll
    for (int t = 0; t < 8; t++)
        #pragma unroll
        for (int j = 0; j < 4; j++) acc[t][j] = 0.f;

    #pragma unroll
    for (int kt = 0; kt < 16; kt++) {
        const int k0 = kt * 8;
        float a0f = sA[row0 * PITCH + k0 + r];
        float a1f = sA[row1 * PITCH + k0 + r];
        float a2f = sA[row0 * PITCH + k0 + 4 + r];
        float a3f = sA[row1 * PITCH + k0 + 4 + r];
        unsigned ah0 = f2tf32(a0f), ah1 = f2tf32(a1f), ah2 = f2tf32(a2f), ah3 = f2tf32(a3f);
        unsigned al0 = f2tf32(a0f - __uint_as_float(ah0));
        unsigned al1 = f2tf32(a1f - __uint_as_float(ah1));
        unsigned al2 = f2tf32(a2f - __uint_as_float(ah2));
        unsigned al3 = f2tf32(a3f - __uint_as_float(ah3));

        #pragma unroll
        for (int t = 0; t < 8; t++) {
            const unsigned* bhp = sBh + (t * 8 + g) * PITCH + k0;
            const unsigned* blp = sBl + (t * 8 + g) * PITCH + k0;
            unsigned bh0 = bhp[r], bh1 = bhp[4 + r];
            unsigned bl0 = blp[r], bl1 = blp[4 + r];
            asm("mma.sync.aligned.m16n8k8.row.col.f32.tf32.tf32.f32 "
                "{%0,%1,%2,%3},{%4,%5,%6,%7},{%8,%9},{%0,%1,%2,%3};"
                : "+f"(acc[t][0]), "+f"(acc[t][1]), "+f"(acc[t][2]), "+f"(acc[t][3])
                : "r"(ah0), "r"(ah1), "r"(ah2), "r"(ah3), "r"(bh0), "r"(bh1));
            asm("mma.sync.aligned.m16n8k8.row.col.f32.tf32.tf32.f32 "
                "{%0,%1,%2,%3},{%4,%5,%6,%7},{%8,%9},{%0,%1,%2,%3};"
                : "+f"(acc[t][0]), "+f"(acc[t][1]), "+f"(acc[t][2]), "+f"(acc[t][3])
                : "r"(al0), "r"(al1), "r"(al2), "r"(al3), "r"(bh0), "r"(bh1));
            asm("mma.sync.aligned.m16n8k8.row.col.f32.tf32.tf32.f32 "
                "{%0,%1,%2,%3},{%4,%5,%6,%7},{%8,%9},{%0,%1,%2,%3};"
                : "+f"(acc[t][0]), "+f"(acc[t][1]), "+f"(acc[t][2]), "+f"(acc[t][3])
                : "r"(ah0), "r"(ah1), "r"(ah2), "r"(ah3), "r"(bl0), "r"(bl1));
        }
    }

    int n0 = node0 + row0;
    int n1 = node0 + row1;
    #pragma unroll
    for (int t = 0; t < 8; t++) {
        int col = t * 8 + 2 * r;
        if (n0 < N)
            *(__half2*)(g_h1h + (size_t)n0 * HID + col) = __floats2half2_rn(acc[t][0], acc[t][1]);
        if (n1 < N)
            *(__half2*)(g_h1h + (size_t)n1 * HID + col) = __floats2half2_rn(acc[t][2], acc[t][3]);
    }
}

// ---------------- agg1 + gemm2 fused (messages pre-scaled) -------------------
__global__ __launch_bounds__(256) void k_agg1f(const float* __restrict__ b1,
                                               const float* __restrict__ W2, int N) {
    __shared__ float xs[8][HID];
    __shared__ float W2s[HID * CLS];
    __shared__ float dd[8];

    const int tid  = threadIdx.x;
    const int warp = tid >> 5;
    const int lane = tid & 31;
    const int node = blockIdx.x * 8 + warp;

    for (int i = tid; i < HID * CLS; i += 256) W2s[i] = W2[i];

    if (node < N) {
        int rs = __ldg(&g_rowstart[node]), re = __ldg(&g_rowstart[node + 1]);
        float dw = g_dinv[node];

        // self term: h1h is pre-scaled, so this is dinv_i * h1[i] already
        float2 acc = __half22float2(((const __half2*)(g_h1h + (size_t)node * HID))[lane]);

        for (int base = rs; base < re; base += 32) {
            int n = re - base;
            int idx = (lane < n) ? g_edge[base + lane] : 0;
            int cnt = n < 32 ? n : 32;
            int j = 0;
            for (; j + 8 <= cnt; j += 8) {
                int s0 = __shfl_sync(0xffffffffu, idx, j);
                int s1 = __shfl_sync(0xffffffffu, idx, j + 1);
                int s2 = __shfl_sync(0xffffffffu, idx, j + 2);
                int s3 = __shfl_sync(0xffffffffu, idx, j + 3);
                int s4 = __shfl_sync(0xffffffffu, idx, j + 4);
                int s5 = __shfl_sync(0xffffffffu, idx, j + 5);
                int s6 = __shfl_sync(0xffffffffu, idx, j + 6);
                int s7 = __shfl_sync(0xffffffffu, idx, j + 7);
                float2 v0 = __half22float2(((const __half2*)(g_h1h + (size_t)s0 * HID))[lane]);
                float2 v1 = __half22float2(((const __half2*)(g_h1h + (size_t)s1 * HID))[lane]);
                float2 v2 = __half22float2(((const __half2*)(g_h1h + (size_t)s2 * HID))[lane]);
                float2 v3 = __half22float2(((const __half2*)(g_h1h + (size_t)s3 * HID))[lane]);
                float2 v4 = __half22float2(((const __half2*)(g_h1h + (size_t)s4 * HID))[lane]);
                float2 v5 = __half22float2(((const __half2*)(g_h1h + (size_t)s5 * HID))[lane]);
                float2 v6 = __half22float2(((const __half2*)(g_h1h + (size_t)s6 * HID))[lane]);
                float2 v7 = __half22float2(((const __half2*)(g_h1h + (size_t)s7 * HID))[lane]);
                acc.x += v0.x + v1.x + v2.x + v3.x + v4.x + v5.x + v6.x + v7.x;
                acc.y += v0.y + v1.y + v2.y + v3.y + v4.y + v5.y + v6.y + v7.y;
            }
            for (; j < cnt; j++) {
                int s = __shfl_sync(0xffffffffu, idx, j);
                float2 v = __half22float2(((const __half2*)(g_h1h + (size_t)s * HID))[lane]);
                acc.x += v.x; acc.y += v.y;
            }
        }

        float2 bb = ((const float2*)b1)[lane];
        xs[warp][2 * lane]     = fmaxf(fmaf(dw, acc.x, bb.x), 0.f);
        xs[warp][2 * lane + 1] = fmaxf(fmaf(dw, acc.y, bb.y), 0.f);
        if (lane == 0) dd[warp] = dw;
    }
    __syncthreads();

    if (tid < 128) {
        int nn  = tid >> 4;
        int cls = tid & 15;
        int gnode = blockIdx.x * 8 + nn;
        if (gnode < N) {
            float a = 0.f;
            #pragma unroll 16
            for (int k = 0; k < HID; k++)
                a += xs[nn][k] * W2s[k * CLS + cls];
            g_h2sh[(size_t)gnode * CLS + cls] = __float2half_rn(a * dd[nn]);
        }
    }
}

// ---------------- agg2 + combine + log_softmax (half2-vectorized) ------------
// 8 lanes per node; lane c holds classes 2c, 2c+1 as one __half2 load.
__global__ __launch_bounds__(256) void k_agg2(const float* __restrict__ b2,
                                              float* __restrict__ out, int N) {
    int g = (blockIdx.x * 256 + threadIdx.x) >> 3;
    int lane = threadIdx.x & 7;
    int seg = (threadIdx.x >> 3) & 3;                  // which 8-lane group
    unsigned mask = 0xFFu << (seg * 8);
    if (g >= N) return;

    int rs = __ldg(&g_rowstart[g]), re = __ldg(&g_rowstart[g + 1]);
    const __half2* h2 = (const __half2*)g_h2sh;

    float2 acc = __half22float2(h2[(size_t)g * 8 + lane]);   // self term

    for (int base = rs; base < re; base += 8) {
        int n = re - base;
        int idx = (lane < n) ? g_edge[base + lane] : 0;
        int cnt = n < 8 ? n : 8;
        int j = 0;
        for (; j + 4 <= cnt; j += 4) {
            int s0 = __shfl_sync(mask, idx, j, 8);
            int s1 = __shfl_sync(mask, idx, j + 1, 8);
            int s2 = __shfl_sync(mask, idx, j + 2, 8);
            int s3 = __shfl_sync(mask, idx, j + 3, 8);
            float2 v0 = __half22float2(h2[(size_t)s0 * 8 + lane]);
            float2 v1 = __half22float2(h2[(size_t)s1 * 8 + lane]);
            float2 v2 = __half22float2(h2[(size_t)s2 * 8 + lane]);
            float2 v3 = __half22float2(h2[(size_t)s3 * 8 + lane]);
            acc.x += v0.x + v1.x + v2.x + v3.x;
            acc.y += v0.y + v1.y + v2.y + v3.y;
        }
        for (; j < cnt; j++) {
            int s = __shfl_sync(mask, idx, j, 8);
            float2 v = __half22float2(h2[(size_t)s * 8 + lane]);
            acc.x += v.x; acc.y += v.y;
        }
    }

    float d = g_dinv[g];
    float2 bb = ((const float2*)b2)[lane];
    float zx = fmaxf(fmaf(d, acc.x, bb.x), 0.f);
    float zy = fmaxf(fmaf(d, acc.y, bb.y), 0.f);

    float m = fmaxf(zx, zy);
    #pragma unroll
    for (int off = 4; off; off >>= 1) m = fmaxf(m, __shfl_xor_sync(mask, m, off, 8));
    float ssum = expf(zx - m) + expf(zy - m);
    #pragma unroll
    for (int off = 4; off; off >>= 1) ssum += __shfl_xor_sync(mask, ssum, off, 8);

    float ls = m + logf(ssum);
    float2 o = make_float2(zx - ls, zy - ls);
    ((float2*)out)[(size_t)g * 8 + lane] = o;
}

// ---------------- launcher ---------------------------------------------------
extern "C" void kernel_launch(void* const* d_in, const int* in_sizes, int n_in,
                              void* d_out, int out_size) {
    const float* x  = (const float*)d_in[0];
    const int*   ei = (const int*)d_in[1];
    const float* W1 = (const float*)d_in[2];
    const float* b1 = (const float*)d_in[3];
    const float* W2 = (const float*)d_in[4];
    const float* b2 = (const float*)d_in[5];
    float* out = (float*)d_out;

    const int N = in_sizes[0] / FIN;       // 100000
    const int E = in_sizes[1] / 2;         // 1600000
    const int* src = ei;
    const int* dst = ei + E;
    const int nb = (N + 1023) / 1024;

    static cudaStream_t s2 = nullptr;
    static cudaEvent_t evFork = nullptr, evCsr = nullptr, evScale = nullptr, evTail = nullptr;
    static int init_done = 0;
    if (!init_done) {
        cudaFuncSetAttribute(k_gemm1, cudaFuncAttributeMaxDynamicSharedMemorySize, GEMM1_SMEM);
        cudaStreamCreateWithFlags(&s2, cudaStreamNonBlocking);
        cudaEventCreateWithFlags(&evFork, cudaEventDisableTiming);
        cudaEventCreateWithFlags(&evCsr, cudaEventDisableTiming);
        cudaEventCreateWithFlags(&evScale, cudaEventDisableTiming);
        cudaEventCreateWithFlags(&evTail, cudaEventDisableTiming);
        init_done = 1;
    }

    // Fork: gemm1 (x,W1 only) on s2, concurrent with the CSR build chain.
    cudaEventRecord(evFork, 0);
    cudaStreamWaitEvent(s2, evFork, 0);
    k_gemm1<<<(N + 63) / 64, 128, GEMM1_SMEM, s2>>>(x, W1, N);

    // CSR build chain on main stream (g_deg is zero at entry per invariant).
    k_deg<<<(E + 255) / 256, 256>>>(dst, E);
    k_scanA<<<nb, 1024>>>(N);
    k_scanC<<<nb, 1024>>>(N, E, nb);
    cudaEventRecord(evCsr, 0);           // dinv + rowstart + cursor ready

    // s2: after gemm1 (stream order) AND scanC (event): scale messages,
    // then restore g_deg == 0 (already consumed by scanC).
    cudaStreamWaitEvent(s2, evCsr, 0);
    k_scale<<<(N * 8 + 255) / 256, 256, 0, s2>>>(N);
    cudaEventRecord(evScale, s2);
    k_tail_zero<<<(N + 255) / 256, 256, 0, s2>>>(N);
    cudaEventRecord(evTail, s2);

    // Main stream: reorder (needs scanC, stream-ordered) concurrent with k_scale.
    k_reorder<<<(E + 255) / 256, 256>>>(src, dst, E);

    // Join: agg1f needs scaled h1h and the sorted edges.
    cudaStreamWaitEvent(0, evScale, 0);

    k_agg1f<<<(N + 7) / 8, 256>>>(b1, W2, N);

    {
        long long units = (long long)N * 8;
        k_agg2<<<(unsigned)((units + 255) / 256), 256>>>(b2, out, N);
    }

    // Re-join s2 so the capture graph is fully joined to the origin stream.
    cudaStreamWaitEvent(0, evTail, 0);
}